// round 2
// baseline (speedup 1.0000x reference)
#include <cuda_runtime.h>
#include <cuda_bf16.h>

// R1 resubmit (R0 failed on broker infra, no kernel signal).
// MoE gate: logits = X[T,2048] @ W^T[2048,64]; top-8 by (logits+bias); weights =
// L1-normalized sigmoid(logits) at the top-8. Output: [T*8 idx as float | T*8 w].
//
// GEMM uses fma.rn.f32x2 packed fp32, pairing along K (even/odd partial sums),
// so both operands are naturally contiguous 64-bit pairs in shared memory.

#define FMA2(c, a, b) asm("fma.rn.f32x2 %0, %1, %2, %0;" : "+l"(c) : "l"(a), "l"(b))

#define TM 8
#define TN 4

__global__ __launch_bounds__(128, 2) void moe_gate_kernel(
    const float* __restrict__ X,
    const float* __restrict__ W,
    const float* __restrict__ bias,
    float* __restrict__ out,
    int w_off)   // offset (elements) of the weight half of the output
{
    // Tiles: BM=64 tokens, BN=64 experts (all), BK=16 k-floats, double buffered.
    __shared__ __align__(16) float  As[2][64][20];   // [buf][token][k] (pad 20)
    __shared__ __align__(16) float2 Bs[2][8][64];    // [buf][k-pair][expert]
    __shared__ float Cs[64][65];                     // logits for top-k phase

    const int tid  = threadIdx.x;        // 0..127
    const int tx   = tid & 15;           // expert-group index
    const int ty   = tid >> 4;           // token-group index
    const int tok0 = blockIdx.x * 64;

    const int m0 = ty * TM;              // 0..56
    const int e0 = tx * TN;              // 0..60

    // Loader mapping: row = tid>>2 (0..31), k-off = (tid&3)*4
    const int lm = tid >> 2;
    const int lk = (tid & 3) * 4;

    const float* aP0 = X + (size_t)(tok0 + lm) * 2048 + lk;
    const float* aP1 = aP0 + (size_t)32 * 2048;
    const float* bP0 = W + (size_t)lm * 2048 + lk;
    const float* bP1 = bP0 + (size_t)32 * 2048;

    unsigned long long acc[TM][TN];
    #pragma unroll
    for (int m = 0; m < TM; ++m)
        #pragma unroll
        for (int e = 0; e < TN; ++e) acc[m][e] = 0ull;

    // ---- preload tile 0 ----
    float4 pa0 = *(const float4*)aP0;
    float4 pa1 = *(const float4*)aP1;
    float4 pb0 = *(const float4*)bP0;
    float4 pb1 = *(const float4*)bP1;
    {
        *(float4*)&As[0][lm][lk]      = pa0;
        *(float4*)&As[0][lm + 32][lk] = pa1;
        const int kk2 = lk >> 1;  // 0,2,4,6
        Bs[0][kk2][lm]          = make_float2(pb0.x, pb0.y);
        Bs[0][kk2 + 1][lm]      = make_float2(pb0.z, pb0.w);
        Bs[0][kk2][lm + 32]     = make_float2(pb1.x, pb1.y);
        Bs[0][kk2 + 1][lm + 32] = make_float2(pb1.z, pb1.w);
    }
    __syncthreads();

    #pragma unroll 1
    for (int t = 0; t < 128; ++t) {
        const int cur = t & 1;
        // prefetch next tile into registers
        if (t < 127) {
            const float* a0 = aP0 + (t + 1) * 16;
            const float* a1 = aP1 + (t + 1) * 16;
            const float* b0 = bP0 + (t + 1) * 16;
            const float* b1 = bP1 + (t + 1) * 16;
            pa0 = *(const float4*)a0;
            pa1 = *(const float4*)a1;
            pb0 = *(const float4*)b0;
            pb1 = *(const float4*)b1;
        }
        // compute current tile: 8 k-pairs
        #pragma unroll
        for (int kk = 0; kk < 8; kk += 2) {
            ulonglong2 b00 = *(const ulonglong2*)(&Bs[cur][kk][e0]);
            ulonglong2 b01 = *(const ulonglong2*)(&Bs[cur][kk][e0 + 2]);
            ulonglong2 b10 = *(const ulonglong2*)(&Bs[cur][kk + 1][e0]);
            ulonglong2 b11 = *(const ulonglong2*)(&Bs[cur][kk + 1][e0 + 2]);
            #pragma unroll
            for (int m = 0; m < TM; ++m) {
                ulonglong2 a2 = *(const ulonglong2*)(&As[cur][m0 + m][kk * 2]);
                FMA2(acc[m][0], a2.x, b00.x);
                FMA2(acc[m][1], a2.x, b00.y);
                FMA2(acc[m][2], a2.x, b01.x);
                FMA2(acc[m][3], a2.x, b01.y);
                FMA2(acc[m][0], a2.y, b10.x);
                FMA2(acc[m][1], a2.y, b10.y);
                FMA2(acc[m][2], a2.y, b11.x);
                FMA2(acc[m][3], a2.y, b11.y);
            }
        }
        if (t < 127) {
            const int nxt = cur ^ 1;
            *(float4*)&As[nxt][lm][lk]      = pa0;
            *(float4*)&As[nxt][lm + 32][lk] = pa1;
            const int kk2 = lk >> 1;
            Bs[nxt][kk2][lm]          = make_float2(pb0.x, pb0.y);
            Bs[nxt][kk2 + 1][lm]      = make_float2(pb0.z, pb0.w);
            Bs[nxt][kk2][lm + 32]     = make_float2(pb1.x, pb1.y);
            Bs[nxt][kk2 + 1][lm + 32] = make_float2(pb1.z, pb1.w);
            __syncthreads();
        }
    }

    // ---- epilogue: reduce packed pairs, stage logits in smem ----
    #pragma unroll
    for (int m = 0; m < TM; ++m)
        #pragma unroll
        for (int e = 0; e < TN; ++e) {
            unsigned long long v = acc[m][e];
            float lo = __uint_as_float((unsigned)(v & 0xffffffffull));
            float hi = __uint_as_float((unsigned)(v >> 32));
            Cs[m0 + m][e0 + e] = lo + hi;
        }
    __syncthreads();

    // ---- top-8 per token; one warp handles 16 tokens ----
    const int lane = tid & 31;
    const int warp = tid >> 5;
    const float blo = bias[lane];
    const float bhi = bias[lane + 32];
    const float NEG_INF = __int_as_float(0xff800000);

    #pragma unroll 1
    for (int tt = 0; tt < 16; ++tt) {
        const int m   = warp * 16 + tt;
        const int tok = tok0 + m;
        const float v0 = Cs[m][lane];
        const float v1 = Cs[m][lane + 32];
        float b0 = v0 + blo;
        float b1 = v1 + bhi;

        float sel_p = 0.0f;
        int   sel_i = 0;

        #pragma unroll
        for (int k = 0; k < 8; ++k) {
            float cv; int ci;
            if (b1 > b0) { cv = b1; ci = lane + 32; }
            else         { cv = b0; ci = lane; }
            #pragma unroll
            for (int off = 16; off; off >>= 1) {
                float ov = __shfl_down_sync(0xffffffffu, cv, off);
                int   oi = __shfl_down_sync(0xffffffffu, ci, off);
                if (ov > cv || (ov == cv && oi < ci)) { cv = ov; ci = oi; }
            }
            ci = __shfl_sync(0xffffffffu, ci, 0);
            // sigmoid of the raw (unbiased) logit of the winner
            float rawcand = (ci & 32) ? v1 : v0;
            float raw = __shfl_sync(0xffffffffu, rawcand, ci & 31);
            float p = 1.0f / (1.0f + __expf(-raw));
            if (lane == k) { sel_p = p; sel_i = ci; }
            // mask the winner out
            if (ci == lane)           b0 = NEG_INF;
            else if (ci == lane + 32) b1 = NEG_INF;
        }

        // L1 normalize over the 8 selected (lanes >= 8 contribute 0)
        float s = sel_p;
        #pragma unroll
        for (int off = 16; off; off >>= 1) s += __shfl_xor_sync(0xffffffffu, s, off);
        s = fmaxf(s, 1e-12f);

        if (lane < 8) {
            out[(size_t)tok * 8 + lane]         = (float)sel_i;
            out[(size_t)w_off + tok * 8 + lane] = sel_p / s;
        }
    }
}

extern "C" void kernel_launch(void* const* d_in, const int* in_sizes, int n_in,
                              void* d_out, int out_size) {
    const float* X    = (const float*)d_in[0];
    const float* W    = (const float*)d_in[1];
    const float* bias = (const float*)d_in[2];
    float* out = (float*)d_out;

    const int T = in_sizes[0] / 2048;   // 16384 tokens
    const int w_off = out_size >> 1;    // weights live in the second half

    moe_gate_kernel<<<T / 64, 128>>>(X, W, bias, out, w_off);
}